// round 4
// baseline (speedup 1.0000x reference)
#include <cuda_runtime.h>

// Volume rendering (NeRF-style) fused kernel.
// Inputs: density (N,64,1) f32 in [0,1), depth_values (N,64) f32 sorted in [2,6],
// rays_feature (N,64,3) f32. Output buffer: feature (N,3) then depth (N).
//
// One warp per ray. cumprod(exp(-x)) == exp(-cumsum(x)) turns the serial
// exclusive cumprod into a warp-parallel exclusive prefix sum.
// Each lane owns points p0=2*lane, p1=2*lane+1 -> all loads coalesced.
//
// CRITICAL fp32 detail: the sentinel delta (1e10) makes lane 31's sd1 ~1e10,
// which would absorb the ~O(1) optical depth in the scan (ulp@1e10 ~ 1024) and
// corrupt excl = scan - local. The sentinel term is NEVER needed in any
// exclusive prefix (point 63 is last), so it is excluded from the scan and
// only used in its own exp(-sd1) (which underflows to 0, matching the ref).

#define N_PTS 64
#define FAR_DELTA 1e10f

__global__ __launch_bounds__(256) void volrend_kernel(
    const float* __restrict__ inA,     // one of {density, depth}
    const float* __restrict__ inB,     // the other
    const float* __restrict__ feat,
    float* __restrict__ out,           // [0, 3N) feature, [3N, 4N) depth
    int n_rays)
{
    const int lane = threadIdx.x & 31;
    const int warp = threadIdx.x >> 5;
    const int ray  = blockIdx.x * (blockDim.x >> 5) + warp;
    if (ray >= n_rays) return;

    // ---- coalesced loads: each lane grabs its pair as float2 ----
    const float2 av = reinterpret_cast<const float2*>(inA + (size_t)ray * N_PTS)[lane];
    const float2 bv = reinterpret_cast<const float2*>(inB + (size_t)ray * N_PTS)[lane];

    // Disambiguate: depth values are in [2,6], density in [0,1). Warp-uniform.
    const bool a_is_depth = (av.x >= 1.5f);
    const float2 dep = a_is_depth ? av : bv;
    const float2 sig = a_is_depth ? bv : av;

    // depth[2*lane+2] lives in the next lane's dep.x
    const float dnext = __shfl_down_sync(0xffffffffu, dep.x, 1);

    const float delta0 = dep.y - dep.x;
    const float delta1 = (lane == 31) ? FAR_DELTA : (dnext - dep.y);
    const float sd0 = sig.x * delta0;
    const float sd1 = sig.y * delta1;

    // ---- exclusive prefix sum of sigma*delta over the 64 points ----
    // Exclude the huge sentinel term from the scan (see header comment).
    const float sd1_scan = (lane == 31) ? 0.0f : sd1;
    const float local = sd0 + sd1_scan;
    float scan = local;
    #pragma unroll
    for (int o = 1; o < 32; o <<= 1) {
        float v = __shfl_up_sync(0xffffffffu, scan, o);
        if (lane >= o) scan += v;
    }
    const float excl = scan - local;          // sum of sd over points < 2*lane

    const float T0 = __expf(-excl);           // transmittance at p0
    const float e0 = __expf(-sd0);
    const float w0 = T0 * (1.0f - e0);
    const float T1 = T0 * e0;                 // transmittance at p1
    const float w1 = T1 * (1.0f - __expf(-sd1));

    // ---- features: 6 floats per lane, contiguous across the warp ----
    const float2* f2 = reinterpret_cast<const float2*>(
        feat + (size_t)ray * (N_PTS * 3) + lane * 6);
    const float2 fa = f2[0];   // p0.x p0.y
    const float2 fb = f2[1];   // p0.z p1.x
    const float2 fc = f2[2];   // p1.y p1.z

    float fx = w0 * fa.x + w1 * fb.y;
    float fy = w0 * fa.y + w1 * fc.x;
    float fz = w0 * fb.x + w1 * fc.y;
    float dd = w0 * dep.x + w1 * dep.y;

    // ---- warp reduction of the 4 accumulators ----
    #pragma unroll
    for (int o = 16; o; o >>= 1) {
        fx += __shfl_xor_sync(0xffffffffu, fx, o);
        fy += __shfl_xor_sync(0xffffffffu, fy, o);
        fz += __shfl_xor_sync(0xffffffffu, fz, o);
        dd += __shfl_xor_sync(0xffffffffu, dd, o);
    }

    if (lane == 0) {
        out[(size_t)ray * 3 + 0] = fx;
        out[(size_t)ray * 3 + 1] = fy;
        out[(size_t)ray * 3 + 2] = fz;
        out[(size_t)n_rays * 3 + ray] = dd;
    }
}

extern "C" void kernel_launch(void* const* d_in, const int* in_sizes, int n_in,
                              void* d_out, int out_size)
{
    // Identify rays_feature by size: it is 3x larger than density/depth.
    int fi = 0;
    for (int i = 1; i < n_in; i++)
        if (in_sizes[i] > in_sizes[fi]) fi = i;
    const int ai = (fi == 0) ? 1 : 0;
    const int bi = 3 - fi - ai;

    const float* A    = (const float*)d_in[ai];
    const float* B    = (const float*)d_in[bi];
    const float* feat = (const float*)d_in[fi];
    float* out = (float*)d_out;

    const int n_rays = out_size / 4;          // out = feature(3N) + depth(N)

    const int threads = 256;                  // 8 warps = 8 rays per block
    const int rays_per_block = threads / 32;
    const int blocks = (n_rays + rays_per_block - 1) / rays_per_block;
    volrend_kernel<<<blocks, threads>>>(A, B, feat, out, n_rays);
}

// round 5
// speedup vs baseline: 1.1934x; 1.1934x over previous
#include <cuda_runtime.h>

// Volume rendering (NeRF-style) fused kernel — v2.
// Inputs: density (N,64,1) f32 in [0,1), depth_values (N,64) f32 sorted in [2,6],
// rays_feature (N,64,3) f32. Output buffer: feature (N,3) then depth (N).
//
// v2 structure: each warp handles TWO rays (16-lane segments), each lane owns
// FOUR consecutive points -> every input load is a float4 (LDG.128), and the
// scan/reduction cost is amortized over 2 rays. Width-16 shfl gives hardware-
// segmented scan/reduction for free.
//
// cumprod(exp(-x)) == exp(-cumsum(x)) turns the serial exclusive cumprod into
// a segmented-parallel exclusive prefix sum.
//
// fp32 detail: the sentinel delta (1e10) at the last point would absorb the
// O(1) optical depth in the scan (ulp@1e10 ~ 1024). It is never needed in any
// exclusive prefix, so it's excluded from the scan and used only in its own
// exp(-sd) (which underflows to 0, matching the reference).

#define N_PTS 64
#define FAR_DELTA 1e10f

__global__ __launch_bounds__(256) void volrend_kernel(
    const float* __restrict__ inA,     // one of {density, depth}
    const float* __restrict__ inB,     // the other
    const float* __restrict__ feat,
    float* __restrict__ out,           // [0, 3N) feature, [3N, 4N) depth
    int n_rays)
{
    const int lane = threadIdx.x & 31;
    const int sl   = lane & 15;                     // lane within ray segment
    const int warp = threadIdx.x >> 5;
    const int ray  = (blockIdx.x * (blockDim.x >> 5) + warp) * 2 + (lane >> 4);
    if (ray >= n_rays) return;

    // ---- float4 streaming loads: lane owns points 4*sl .. 4*sl+3 ----
    const float4 av = __ldcs(reinterpret_cast<const float4*>(inA + (size_t)ray * N_PTS) + sl);
    const float4 bv = __ldcs(reinterpret_cast<const float4*>(inB + (size_t)ray * N_PTS) + sl);

    const float4* f4 = reinterpret_cast<const float4*>(feat + (size_t)ray * (N_PTS * 3)) + sl * 3;
    const float4 fa = __ldcs(f4 + 0);   // f0.x f0.y f0.z f1.x
    const float4 fb = __ldcs(f4 + 1);   // f1.y f1.z f2.x f2.y
    const float4 fc = __ldcs(f4 + 2);   // f2.z f3.x f3.y f3.z

    // Disambiguate: depth in [2,6], density in [0,1). Warp-uniform.
    const bool a_is_depth = (av.x >= 1.5f);
    const float4 dep = a_is_depth ? av : bv;
    const float4 sig = a_is_depth ? bv : av;

    // depth[4*sl+4] lives in the next lane's dep.x (segment-local shfl)
    const float dnext = __shfl_down_sync(0xffffffffu, dep.x, 1, 16);

    const float delta0 = dep.y - dep.x;
    const float delta1 = dep.z - dep.y;
    const float delta2 = dep.w - dep.z;
    const float delta3 = (sl == 15) ? FAR_DELTA : (dnext - dep.w);
    const float sd0 = sig.x * delta0;
    const float sd1 = sig.y * delta1;
    const float sd2 = sig.z * delta2;
    const float sd3 = sig.w * delta3;

    // ---- segmented exclusive prefix sum of sigma*delta (width 16) ----
    // Exclude the huge sentinel term from the scan (see header comment).
    const float local = sd0 + sd1 + sd2 + ((sl == 15) ? 0.0f : sd3);
    float scan = local;
    #pragma unroll
    for (int o = 1; o < 16; o <<= 1) {
        float v = __shfl_up_sync(0xffffffffu, scan, o, 16);
        if (sl >= o) scan += v;
    }
    const float excl = scan - local;          // sum of sd over points < 4*sl

    const float T0 = __expf(-excl);
    const float e0 = __expf(-sd0);
    const float e1 = __expf(-sd1);
    const float e2 = __expf(-sd2);
    const float e3 = __expf(-sd3);            // underflows to 0 at sl==15
    const float w0 = T0 * (1.0f - e0);
    const float T1 = T0 * e0;
    const float w1 = T1 * (1.0f - e1);
    const float T2 = T1 * e1;
    const float w2 = T2 * (1.0f - e2);
    const float T3 = T2 * e2;
    const float w3 = T3 * (1.0f - e3);

    float fx = w0 * fa.x + w1 * fa.w + w2 * fb.z + w3 * fc.y;
    float fy = w0 * fa.y + w1 * fb.x + w2 * fb.w + w3 * fc.z;
    float fz = w0 * fa.z + w1 * fb.y + w2 * fc.x + w3 * fc.w;
    float dd = w0 * dep.x + w1 * dep.y + w2 * dep.z + w3 * dep.w;

    // ---- segmented butterfly reduction (width 16) ----
    #pragma unroll
    for (int o = 8; o; o >>= 1) {
        fx += __shfl_xor_sync(0xffffffffu, fx, o, 16);
        fy += __shfl_xor_sync(0xffffffffu, fy, o, 16);
        fz += __shfl_xor_sync(0xffffffffu, fz, o, 16);
        dd += __shfl_xor_sync(0xffffffffu, dd, o, 16);
    }

    if (sl == 0) {
        out[(size_t)ray * 3 + 0] = fx;
        out[(size_t)ray * 3 + 1] = fy;
        out[(size_t)ray * 3 + 2] = fz;
        out[(size_t)n_rays * 3 + ray] = dd;
    }
}

extern "C" void kernel_launch(void* const* d_in, const int* in_sizes, int n_in,
                              void* d_out, int out_size)
{
    // Identify rays_feature by size: it is 3x larger than density/depth.
    int fi = 0;
    for (int i = 1; i < n_in; i++)
        if (in_sizes[i] > in_sizes[fi]) fi = i;
    const int ai = (fi == 0) ? 1 : 0;
    const int bi = 3 - fi - ai;

    const float* A    = (const float*)d_in[ai];
    const float* B    = (const float*)d_in[bi];
    const float* feat = (const float*)d_in[fi];
    float* out = (float*)d_out;

    const int n_rays = out_size / 4;          // out = feature(3N) + depth(N)

    const int threads = 256;                  // 8 warps = 16 rays per block
    const int rays_per_block = (threads / 32) * 2;
    const int blocks = (n_rays + rays_per_block - 1) / rays_per_block;
    volrend_kernel<<<blocks, threads>>>(A, B, feat, out, n_rays);
}